// round 1
// baseline (speedup 1.0000x reference)
#include <cuda_runtime.h>
#include <stdint.h>
#include <math.h>

#define NTOT   (1<<22)
#define NBANDS 8
#define TPB    256
#define NBLK   512
#define CHUNK  (NTOT/NBLK)   /* 8192 */
#define LSEG   (CHUNK/TPB)   /* 32   */
#define GT     (NBLK*TPB)    /* 131072 */

// ---------------- static device scratch (no allocations allowed) ----------------
__device__ unsigned long long g_key[NTOT];           // per-band sorted (key,idx)
__device__ int    g_bcnt[NBLK*NBANDS];
__device__ int    g_boff[NBLK*NBANDS];
__device__ int    g_base[NBANDS+1];
__device__ float  g_st[NTOT], g_sa[NTOT], g_sy[NTOT], g_sd[NTOT]; // sorted t, amp, y, diag
__device__ float  g_Darr[NTOT], g_Warr[NTOT];
__device__ double g_thrM[GT*4], g_blkM[NBLK*4], g_blkMex[NBLK*4];
__device__ double g_thrA[GT*2], g_blkA[NBLK*2], g_blkAex[NBLK*2];
__device__ double g_bsum[NBLK];
__device__ float  g_amps[NBANDS], g_lags[NBANDS], g_ka, g_kc;

__device__ __forceinline__ unsigned fkey(float f){
    unsigned u = __float_as_uint(f);
    return (u & 0x80000000u) ? ~u : (u | 0x80000000u);
}

__device__ __forceinline__ void mmulD(double r[4], const double n[4], const double o[4]){
    double t0 = n[0]*o[0] + n[1]*o[2];
    double t1 = n[0]*o[1] + n[1]*o[3];
    double t2 = n[2]*o[0] + n[3]*o[2];
    double t3 = n[2]*o[1] + n[3]*o[3];
    double mx = fmax(fmax(fabs(t0),fabs(t1)), fmax(fabs(t2),fabs(t3)));
    double s  = (mx > 0.0) ? 1.0/mx : 1.0;
    r[0]=t0*s; r[1]=t1*s; r[2]=t2*s; r[3]=t3*s;
}

// ---------------- param setup ----------------
__global__ void k_init(const float* __restrict__ lad, const float* __restrict__ lg,
                       const float* __restrict__ lkp){
    if (threadIdx.x == 0){
        g_amps[0] = 1.f; g_lags[0] = 0.f;
        for (int b = 1; b < NBANDS; b++){
            g_amps[b] = expf(lad[b-1]);
            g_lags[b] = lg[b-1];
        }
        g_ka = expf(lkp[0]);
        g_kc = expf(lkp[1]);
    }
}

// ---------------- stage 1: stable partition by band ----------------
__global__ void k_count(const int* __restrict__ band){
    int cnt[NBANDS];
    #pragma unroll
    for (int b = 0; b < NBANDS; b++) cnt[b] = 0;
    int base = blockIdx.x * CHUNK;
    for (int i = threadIdx.x; i < CHUNK; i += TPB) cnt[band[base+i]]++;
    __shared__ int sc[NBANDS];
    if (threadIdx.x < NBANDS) sc[threadIdx.x] = 0;
    __syncthreads();
    #pragma unroll
    for (int b = 0; b < NBANDS; b++) if (cnt[b]) atomicAdd(&sc[b], cnt[b]);
    __syncthreads();
    if (threadIdx.x < NBANDS) g_bcnt[blockIdx.x*NBANDS + threadIdx.x] = sc[threadIdx.x];
}

__global__ void k_offsets(){
    __shared__ int tot[NBANDS];
    __shared__ int bb[NBANDS+1];
    int tid = threadIdx.x;
    if (tid < NBANDS){
        int run = 0;
        for (int blk = 0; blk < NBLK; blk++){
            int c = g_bcnt[blk*NBANDS + tid];
            g_boff[blk*NBANDS + tid] = run;
            run += c;
        }
        tot[tid] = run;
    }
    __syncthreads();
    if (tid == 0){
        int s = 0;
        for (int b = 0; b < NBANDS; b++){ bb[b] = s; g_base[b] = s; s += tot[b]; }
        bb[NBANDS] = s; g_base[NBANDS] = s;
    }
    __syncthreads();
    for (int idx = tid; idx < NBLK*NBANDS; idx += TPB)
        g_boff[idx] += bb[idx & (NBANDS-1)];
}

__global__ void k_scatter(const float* __restrict__ t, const int* __restrict__ band){
    int tid  = threadIdx.x;
    int base = blockIdx.x * CHUNK + tid * LSEG;
    int cnt[NBANDS];
    #pragma unroll
    for (int b = 0; b < NBANDS; b++) cnt[b] = 0;
    int bl[LSEG];
    #pragma unroll
    for (int j = 0; j < LSEG; j++){ int b = band[base+j]; bl[j] = b; cnt[b]++; }

    __shared__ int s[NBANDS*TPB];
    #pragma unroll
    for (int b = 0; b < NBANDS; b++) s[b*TPB + tid] = cnt[b];
    __syncthreads();
    for (int off = 1; off < TPB; off <<= 1){
        int v[NBANDS];
        #pragma unroll
        for (int b = 0; b < NBANDS; b++) v[b] = (tid >= off) ? s[b*TPB + tid - off] : 0;
        __syncthreads();
        #pragma unroll
        for (int b = 0; b < NBANDS; b++) s[b*TPB + tid] += v[b];
        __syncthreads();
    }
    int pos[NBANDS];
    #pragma unroll
    for (int b = 0; b < NBANDS; b++)
        pos[b] = g_boff[blockIdx.x*NBANDS + b] + (tid ? s[b*TPB + tid - 1] : 0);

    #pragma unroll
    for (int j = 0; j < LSEG; j++){
        int i = base + j; int b = bl[j];
        float nt = t[i] - g_lags[b];
        unsigned long long k = ((unsigned long long)fkey(nt) << 32) | (unsigned)i;
        g_key[pos[b]++] = k;
    }
}

// ---------------- stage 2: merge rank via binary search + gather sorted arrays ----------------
__global__ void k_rank(const float* __restrict__ t, const float* __restrict__ y,
                       const float* __restrict__ dg){
    int j = blockIdx.x * blockDim.x + threadIdx.x;
    if (j >= NTOT) return;
    unsigned long long key = g_key[j];
    int b = 0;
    while (b < NBANDS-1 && j >= g_base[b+1]) b++;
    int rank = j - g_base[b];
    #pragma unroll
    for (int b2 = 0; b2 < NBANDS; b2++){
        if (b2 == b) continue;
        int lo = g_base[b2], hi = g_base[b2+1];
        while (lo < hi){
            int mid = (lo + hi) >> 1;
            if (g_key[mid] < key) lo = mid + 1; else hi = mid;
        }
        rank += lo - g_base[b2];
    }
    unsigned idx = (unsigned)(key & 0xffffffffu);
    float nt = t[idx] - g_lags[b];
    g_st[rank] = nt;
    g_sa[rank] = g_amps[b];
    g_sy[rank] = y[idx];
    g_sd[rank] = dg[idx];
}

// ---------------- stage 3a: S-scan (Mobius / 2x2 matrix scan) ----------------
__global__ void k_sreduce(){
    int tid = threadIdx.x;
    int gtid = blockIdx.x * TPB + tid;
    int base = gtid * LSEG;
    float a = g_ka, c = g_kc;
    float m0=1.f, m1=0.f, m2=0.f, m3=1.f;
    float tprev = (base > 0) ? g_st[base-1] : g_st[0];
    #pragma unroll 4
    for (int j = 0; j < LSEG; j++){
        int i = base + j;
        float tc = g_st[i];
        float dt = (i > 0) ? (tc - tprev) : 0.f;
        tprev = tc;
        float phi = expf(-c * dt);
        float phi2 = phi * phi;
        float amp = g_sa[i];
        float U = a * amp, V = amp;
        float A = g_sd[i] + U * V;
        float e00 = (A - 2.f*U*V) * phi2, e01 = V*V, e10 = -U*U*phi2, e11 = A;
        float r0 = e00*m0 + e01*m2, r1 = e00*m1 + e01*m3;
        float r2 = e10*m0 + e11*m2, r3 = e10*m1 + e11*m3;
        float mx = fmaxf(fmaxf(fabsf(r0),fabsf(r1)), fmaxf(fabsf(r2),fabsf(r3)));
        float s = (mx > 0.f) ? 1.f/mx : 1.f;
        m0=r0*s; m1=r1*s; m2=r2*s; m3=r3*s;
    }
    __shared__ double sm[TPB*4];
    sm[tid*4+0]=m0; sm[tid*4+1]=m1; sm[tid*4+2]=m2; sm[tid*4+3]=m3;
    __syncthreads();
    for (int off = 1; off < TPB; off <<= 1){
        double p[4]; int h = (tid >= off);
        if (h){ for (int k=0;k<4;k++) p[k] = sm[(tid-off)*4+k]; }
        __syncthreads();
        if (h){
            double cur[4]; for (int k=0;k<4;k++) cur[k] = sm[tid*4+k];
            double r[4]; mmulD(r, cur, p);
            for (int k=0;k<4;k++) sm[tid*4+k] = r[k];
        }
        __syncthreads();
    }
    if (tid == 0){
        g_thrM[gtid*4+0]=1.0; g_thrM[gtid*4+1]=0.0; g_thrM[gtid*4+2]=0.0; g_thrM[gtid*4+3]=1.0;
    } else {
        for (int k=0;k<4;k++) g_thrM[gtid*4+k] = sm[(tid-1)*4+k];
    }
    if (tid == TPB-1){ for (int k=0;k<4;k++) g_blkM[blockIdx.x*4+k] = sm[tid*4+k]; }
}

__global__ void k_blkscanM(){
    __shared__ double sm[NBLK*4];
    int tid = threadIdx.x;
    for (int k=0;k<4;k++) sm[tid*4+k] = g_blkM[tid*4+k];
    __syncthreads();
    for (int off = 1; off < NBLK; off <<= 1){
        double p[4]; int h = (tid >= off);
        if (h){ for (int k=0;k<4;k++) p[k] = sm[(tid-off)*4+k]; }
        __syncthreads();
        if (h){
            double cur[4]; for (int k=0;k<4;k++) cur[k] = sm[tid*4+k];
            double r[4]; mmulD(r, cur, p);
            for (int k=0;k<4;k++) sm[tid*4+k] = r[k];
        }
        __syncthreads();
    }
    if (tid == 0){
        g_blkMex[0]=1.0; g_blkMex[1]=0.0; g_blkMex[2]=0.0; g_blkMex[3]=1.0;
    } else {
        for (int k=0;k<4;k++) g_blkMex[tid*4+k] = sm[(tid-1)*4+k];
    }
}

// ---------------- stage 3b: apply S, emit D/W, build f-affine scan ----------------
__global__ void k_sapply(){
    int tid = threadIdx.x;
    int gtid = blockIdx.x * TPB + tid;
    int base = gtid * LSEG;
    double Pt[4], Pb[4], E[4];
    for (int k=0;k<4;k++){ Pt[k]=g_thrM[gtid*4+k]; Pb[k]=g_blkMex[blockIdx.x*4+k]; }
    mmulD(E, Pt, Pb);
    float Sp = (float)(E[1] / E[3]);
    float a = g_ka, c = g_kc;
    float al = 1.f, be = 0.f;
    float tprev = (base > 0) ? g_st[base-1] : g_st[0];
    #pragma unroll 4
    for (int j = 0; j < LSEG; j++){
        int i = base + j;
        float tc = g_st[i];
        float dt = (i > 0) ? (tc - tprev) : 0.f;
        tprev = tc;
        float phi = expf(-c * dt);
        float phi2 = phi * phi;
        float amp = g_sa[i];
        float U = a * amp, V = amp;
        float A = g_sd[i] + U * V;
        float S = phi2 * Sp;
        float D = A - U*U*S;
        float W = (V - U*S) / D;
        g_Darr[i] = D; g_Warr[i] = W;
        float an = phi * (1.f - W*U);
        float bn = W * g_sy[i];
        be = an*be + bn;
        al = an*al;
        Sp = S + D*W*W;
    }
    __shared__ double sa[TPB*2];
    sa[tid*2] = (double)al; sa[tid*2+1] = (double)be;
    __syncthreads();
    for (int off = 1; off < TPB; off <<= 1){
        double pa=0.0, pb=0.0; int h = (tid >= off);
        if (h){ pa = sa[(tid-off)*2]; pb = sa[(tid-off)*2+1]; }
        __syncthreads();
        if (h){
            double ca = sa[tid*2], cb = sa[tid*2+1];
            sa[tid*2] = ca*pa; sa[tid*2+1] = ca*pb + cb;
        }
        __syncthreads();
    }
    if (tid == 0){ g_thrA[gtid*2]=1.0; g_thrA[gtid*2+1]=0.0; }
    else { g_thrA[gtid*2]=sa[(tid-1)*2]; g_thrA[gtid*2+1]=sa[(tid-1)*2+1]; }
    if (tid == TPB-1){ g_blkA[blockIdx.x*2]=sa[tid*2]; g_blkA[blockIdx.x*2+1]=sa[tid*2+1]; }
}

__global__ void k_blkscanA(){
    __shared__ double sa[NBLK*2];
    int tid = threadIdx.x;
    sa[tid*2]   = g_blkA[tid*2];
    sa[tid*2+1] = g_blkA[tid*2+1];
    __syncthreads();
    for (int off = 1; off < NBLK; off <<= 1){
        double pa=0.0, pb=0.0; int h = (tid >= off);
        if (h){ pa = sa[(tid-off)*2]; pb = sa[(tid-off)*2+1]; }
        __syncthreads();
        if (h){
            double ca = sa[tid*2], cb = sa[tid*2+1];
            sa[tid*2] = ca*pa; sa[tid*2+1] = ca*pb + cb;
        }
        __syncthreads();
    }
    if (tid == 0){ g_blkAex[0]=1.0; g_blkAex[1]=0.0; }
    else { g_blkAex[tid*2]=sa[(tid-1)*2]; g_blkAex[tid*2+1]=sa[(tid-1)*2+1]; }
}

// ---------------- stage 3c: apply f, compute z, reduce ----------------
__global__ void k_fapply(){
    int tid = threadIdx.x;
    int gtid = blockIdx.x * TPB + tid;
    int base = gtid * LSEG;
    double ta = g_thrA[gtid*2],        tb = g_thrA[gtid*2+1];
    double bb = g_blkAex[blockIdx.x*2+1];
    float f = (float)(ta*bb + tb);
    float a = g_ka, c = g_kc;
    double loc = 0.0;
    float tprev = (base > 0) ? g_st[base-1] : g_st[0];
    #pragma unroll 4
    for (int j = 0; j < LSEG; j++){
        int i = base + j;
        float tc = g_st[i];
        float dt = (i > 0) ? (tc - tprev) : 0.f;
        tprev = tc;
        float phi = expf(-c * dt);
        float U = a * g_sa[i];
        float fin = phi * f;
        float z = g_sy[i] - U * fin;
        float W = g_Warr[i], D = g_Darr[i];
        f = fin + W * z;
        loc += (double)(z*z / D) + (double)logf(D);
    }
    __shared__ double red[TPB];
    red[tid] = loc;
    __syncthreads();
    for (int off = TPB/2; off > 0; off >>= 1){
        if (tid < off) red[tid] += red[tid+off];
        __syncthreads();
    }
    if (tid == 0) g_bsum[blockIdx.x] = red[0];
}

__global__ void k_final(float* out, int N){
    if (threadIdx.x == 0){
        double s = 0.0;
        for (int i = 0; i < NBLK; i++) s += g_bsum[i];
        out[0] = (float)(0.5 * (s + (double)N * 1.8378770664093454));
    }
}

// ---------------- launch ----------------
extern "C" void kernel_launch(void* const* d_in, const int* in_sizes, int n_in,
                              void* d_out, int out_size){
    const float* t    = (const float*)d_in[0];
    const int*   band = (const int*)  d_in[1];
    const float* y    = (const float*)d_in[2];
    const float* dg   = (const float*)d_in[3];
    const float* lad  = (const float*)d_in[4];
    const float* lg   = (const float*)d_in[5];
    const float* lkp  = (const float*)d_in[6];
    float* out = (float*)d_out;
    int N = in_sizes[0];  // expected NTOT

    k_init    <<<1, 32>>>(lad, lg, lkp);
    k_count   <<<NBLK, TPB>>>(band);
    k_offsets <<<1, TPB>>>();
    k_scatter <<<NBLK, TPB>>>(t, band);
    k_rank    <<<NTOT/TPB, TPB>>>(t, y, dg);
    k_sreduce <<<NBLK, TPB>>>();
    k_blkscanM<<<1, NBLK>>>();
    k_sapply  <<<NBLK, TPB>>>();
    k_blkscanA<<<1, NBLK>>>();
    k_fapply  <<<NBLK, TPB>>>();
    k_final   <<<1, 32>>>(out, N);
}